// round 13
// baseline (speedup 1.0000x reference)
#include <cuda_runtime.h>
#include <cuda_bf16.h>
#include <cuda_fp16.h>

#define MAX_NODES 100000
#define MAX_EDGES 1600000
#define CAP 64   // max neighbors stored per node; deg ~ Poisson(16), P(>64) ~ 1e-20

// ---------------- scratch (device globals; no allocation allowed) ----------
// Gather tables use rows 1..n for real nodes; ROW 0 IS THE DUMMY ZERO ROW.
// CSR pad value is 0 -> matches static zero-init; reset kernel restores the
// zero state at the end of every replay.
__device__                int    g_cnt[MAX_NODES];                 // in-degree
__device__ __align__(16)  int    g_csr[MAX_NODES * CAP];           // src+1 lists
__device__ __align__(16)  __half g_Pl_h[(MAX_NODES + 1) * 16];     // pl fp16 (row0=dummy)
__device__ __align__(16)  float  g_Pr[MAX_NODES * 16];             // pr fp32
__device__ __align__(16)  __half g_h16[(MAX_NODES + 1) * 16];      // h fp16 (row0=dummy)

// ---------------- K1: build bucketed CSR (one pass, 2 edges/thread) --------
__global__ void __launch_bounds__(256)
build_kernel(const int* __restrict__ ei, int E) {
    int i = blockIdx.x * blockDim.x + threadIdx.x;   // pair index
    int base = i * 2;
    if (base >= E) return;
    if (base + 1 < E) {
        int2 s2 = *(const int2*)&ei[base];
        int2 d2 = *(const int2*)&ei[E + base];
        int p0 = atomicAdd(&g_cnt[d2.x], 1);
        int p1 = atomicAdd(&g_cnt[d2.y], 1);
        if (p0 < CAP) g_csr[(size_t)d2.x * CAP + p0] = s2.x + 1;
        if (p1 < CAP) g_csr[(size_t)d2.y * CAP + p1] = s2.y + 1;
    } else {
        int src = ei[base];
        int dst = ei[E + base];
        int p = atomicAdd(&g_cnt[dst], 1);
        if (p < CAP) g_csr[(size_t)dst * CAP + p] = src + 1;
    }
}

// ---------------- K6: reset for next replay ---------------------------------
__global__ void __launch_bounds__(256)
reset_kernel(int n) {
    int tid = blockIdx.x * blockDim.x + threadIdx.x;
    int stride = gridDim.x * blockDim.x;
    for (int i = tid; i < n; i += stride) g_cnt[i] = 0;
    int4 z4 = make_int4(0, 0, 0, 0);
    int tot = n * 8;                       // 8 int4 cover slots 0..31
    for (int i = tid; i < tot; i += stride) {
        int node = i >> 3, q = i & 7;
        ((int4*)&g_csr[(size_t)node * CAP])[q] = z4;
    }
}

// ---------------- bf16 split helper (for gemm1 inputs) ----------------------
__device__ __forceinline__ unsigned split_pack(float v0, float v1, unsigned& lo_out) {
    __nv_bfloat16 h0 = __float2bfloat16_rn(v0);
    __nv_bfloat16 h1 = __float2bfloat16_rn(v1);
    float r0 = v0 - __bfloat162float(h0);
    float r1 = v1 - __bfloat162float(h1);
    __nv_bfloat16 l0 = __float2bfloat16_rn(r0);
    __nv_bfloat16 l1 = __float2bfloat16_rn(r1);
    lo_out = (unsigned)__bfloat16_as_ushort(l0) | ((unsigned)__bfloat16_as_ushort(l1) << 16);
    return (unsigned)__bfloat16_as_ushort(h0) | ((unsigned)__bfloat16_as_ushort(h1) << 16);
}

__device__ __forceinline__ void mma_bf16(float c[4], unsigned a0, unsigned a1,
                                         unsigned a2, unsigned a3,
                                         unsigned b0, unsigned b1) {
    asm volatile(
        "mma.sync.aligned.m16n8k16.row.col.f32.bf16.bf16.f32 "
        "{%0,%1,%2,%3}, {%4,%5,%6,%7}, {%8,%9}, {%0,%1,%2,%3};"
        : "+f"(c[0]), "+f"(c[1]), "+f"(c[2]), "+f"(c[3])
        : "r"(a0), "r"(a1), "r"(a2), "r"(a3), "r"(b0), "r"(b1));
}

// ---------------- K2: P = x @ [W1l | W1r] via bf16-split tensor cores ------
__global__ void __launch_bounds__(256)
gemm1_kernel(const float* __restrict__ x,
             const float* __restrict__ W1l,
             const float* __restrict__ W1r, int n) {
    __shared__ unsigned sBhi[2048];
    __shared__ unsigned sBlo[2048];
    for (int idx = threadIdx.x; idx < 2048; idx += 256) {
        int lane  = idx & 31;
        int r     = (idx >> 5) & 1;
        int ntile = (idx >> 6) & 3;
        int kstep = idx >> 8;
        int t = lane & 3, gg = lane >> 2;
        int k = kstep * 16 + 2 * t + 8 * r;
        int j = ntile * 8 + gg;
        float w0 = (j < 16) ? W1l[k * 16 + j]       : W1r[k * 16 + (j - 16)];
        float w1 = (j < 16) ? W1l[(k + 1) * 16 + j] : W1r[(k + 1) * 16 + (j - 16)];
        unsigned lo;
        unsigned hi = split_pack(w0, w1, lo);
        sBhi[idx] = hi;
        sBlo[idx] = lo;
    }
    __syncthreads();

    int warp = threadIdx.x >> 5;
    int lane = threadIdx.x & 31;
    int row0 = (blockIdx.x * 8 + warp) * 16;
    if (row0 >= n) return;
    int g = lane >> 2;
    int t = lane & 3;

    int rA = row0 + g;      if (rA >= n) rA = n - 1;
    int rB = row0 + g + 8;  if (rB >= n) rB = n - 1;

    const float2* x2 = (const float2*)x;
    float c[4][4];
#pragma unroll
    for (int nt = 0; nt < 4; nt++)
#pragma unroll
        for (int q = 0; q < 4; q++) c[nt][q] = 0.f;

#pragma unroll
    for (int kstep = 0; kstep < 8; kstep++) {
        float2 p00 = x2[(size_t)rA * 64 + kstep * 8 + t];
        float2 p01 = x2[(size_t)rA * 64 + kstep * 8 + t + 4];
        float2 p10 = x2[(size_t)rB * 64 + kstep * 8 + t];
        float2 p11 = x2[(size_t)rB * 64 + kstep * 8 + t + 4];
        unsigned alo0, alo1, alo2, alo3;
        unsigned ahi0 = split_pack(p00.x, p00.y, alo0);
        unsigned ahi1 = split_pack(p10.x, p10.y, alo1);
        unsigned ahi2 = split_pack(p01.x, p01.y, alo2);
        unsigned ahi3 = split_pack(p11.x, p11.y, alo3);

#pragma unroll
        for (int nt = 0; nt < 4; nt++) {
            int base = ((kstep * 4 + nt) * 2) * 32 + lane;
            unsigned bhi0 = sBhi[base], bhi1 = sBhi[base + 32];
            unsigned blo0 = sBlo[base], blo1 = sBlo[base + 32];
            mma_bf16(c[nt], ahi0, ahi1, ahi2, ahi3, bhi0, bhi1);
            mma_bf16(c[nt], ahi0, ahi1, ahi2, ahi3, blo0, blo1);
            mma_bf16(c[nt], alo0, alo1, alo2, alo3, bhi0, bhi1);
        }
    }

    // pl -> fp16 table (shifted by +1 row); pr -> fp32 table
#pragma unroll
    for (int nt = 0; nt < 2; nt++) {        // cols 0..15 (pl)
        int j0 = nt * 8 + 2 * t;
        if (row0 + g < n) {
            __half2 hp = __float22half2_rn(make_float2(c[nt][0], c[nt][1]));
            *(__half2*)&g_Pl_h[(size_t)(row0 + g + 1) * 16 + j0] = hp;
        }
        if (row0 + g + 8 < n) {
            __half2 hp = __float22half2_rn(make_float2(c[nt][2], c[nt][3]));
            *(__half2*)&g_Pl_h[(size_t)(row0 + g + 9) * 16 + j0] = hp;
        }
    }
#pragma unroll
    for (int nt = 2; nt < 4; nt++) {        // cols 16..31 (pr)
        int j0 = (nt - 2) * 8 + 2 * t;
        if (row0 + g < n)
            *(float2*)&g_Pr[(size_t)(row0 + g) * 16 + j0] = make_float2(c[nt][0], c[nt][1]);
        if (row0 + g + 8 < n)
            *(float2*)&g_Pr[(size_t)(row0 + g + 8) * 16 + j0] = make_float2(c[nt][2], c[nt][3]);
    }
}

// ---------------- K3: agg1 + finish1 fused (R10 gather shape) ---------------
// h written ONLY to the fp16 table (consumed by the fused layer-2 kernel).
__global__ void __launch_bounds__(256)
agg1_kernel(const float* __restrict__ b1, int n) {
    int warpId = (blockIdx.x * blockDim.x + threadIdx.x) >> 5;
    int node0 = warpId * 2;
    if (node0 >= n) return;
    int lane = threadIdx.x & 31;
    int half = lane >> 4;
    int l    = lane & 15;
    int grp  = l >> 2;
    int comp = l & 3;

    int node  = node0 + half;
    bool valid = node < n;
    int nodeC = valid ? node : node0;

    int deg0 = __ldg(&g_cnt[nodeC]);

    const uint2* __restrict__ Ph  = (const uint2*)g_Pl_h;
    const int*   __restrict__ row = &g_csr[(size_t)nodeC * CAP];

    int idxA = __ldg(&row[l]);
    int idxB = __ldg(&row[l + 16]);

    float4 acc = make_float4(0.f, 0.f, 0.f, 0.f);
#pragma unroll
    for (int k = 0; k < 8; k++) {
        int s = grp + 4 * k;
        int src = (s < 16)
            ? __shfl_sync(0xffffffffu, idxA, (half << 4) | s)
            : __shfl_sync(0xffffffffu, idxB, (half << 4) | (s - 16));
        uint2 raw = __ldg(&Ph[(size_t)src * 4 + comp]);
        float2 f01 = __half22float2(*(__half2*)&raw.x);
        float2 f23 = __half22float2(*(__half2*)&raw.y);
        acc.x += f01.x; acc.y += f01.y; acc.z += f23.x; acc.w += f23.y;
    }
    if (deg0 > 32) {
        int dmax = deg0 < CAP ? deg0 : CAP;
        for (int s = 32 + grp; s < dmax; s += 4) {
            int src = __ldg(&row[s]);
            uint2 raw = __ldg(&Ph[(size_t)src * 4 + comp]);
            float2 f01 = __half22float2(*(__half2*)&raw.x);
            float2 f23 = __half22float2(*(__half2*)&raw.y);
            acc.x += f01.x; acc.y += f01.y; acc.z += f23.x; acc.w += f23.y;
        }
    }
#pragma unroll
    for (int off = 4; off < 16; off <<= 1) {
        acc.x += __shfl_xor_sync(0xffffffffu, acc.x, off);
        acc.y += __shfl_xor_sync(0xffffffffu, acc.y, off);
        acc.z += __shfl_xor_sync(0xffffffffu, acc.z, off);
        acc.w += __shfl_xor_sync(0xffffffffu, acc.w, off);
    }
    if (l < 4 && valid) {
        float inv = 1.f / fmaxf((float)deg0, 1.f);
        float4 pr = ((const float4*)g_Pr)[(size_t)node * 4 + l];
        float4 bb = ((const float4*)b1)[l];
        float4 hv;
        hv.x = fmaxf(fmaf(acc.x, inv, bb.x + pr.x), 0.f);
        hv.y = fmaxf(fmaf(acc.y, inv, bb.y + pr.y), 0.f);
        hv.z = fmaxf(fmaf(acc.z, inv, bb.z + pr.z), 0.f);
        hv.w = fmaxf(fmaf(acc.w, inv, bb.w + pr.w), 0.f);
        uint2 packed;
        __half2 p01 = __float22half2_rn(make_float2(hv.x, hv.y));
        __half2 p23 = __float22half2_rn(make_float2(hv.z, hv.w));
        packed.x = *(unsigned*)&p01;
        packed.y = *(unsigned*)&p23;
        ((uint2*)g_h16)[(size_t)(node + 1) * 4 + l] = packed;
    }
}

// ---------------- K4: fused agg2 + logits + log_softmax ---------------------
// Phase A: R10-shape gather of h16 (2 nodes/warp -> 16 nodes/block), stage
//          f = [mean_agg(16) | h(16)] per node in smem.
// Phase B: logits = f @ [W2l|W2r] + b2 via smem float4 quads (160 work items).
// Phase C: per-node log_softmax (16 threads, serial over 40 from smem).
// Phase D: block-coalesced store.
__global__ void __launch_bounds__(256)
agg2f_kernel(const float* __restrict__ W2l,
             const float* __restrict__ b2,
             const float* __restrict__ W2r,
             float* __restrict__ out, int n) {
    __shared__ float sW[32 * 40];     // rows 0..15 = W2l, rows 16..31 = W2r
    __shared__ float sB[40];
    __shared__ float sF[16 * 36];     // per-node f (stride 36: 16B-aligned, skewed)
    __shared__ float sL[16 * 41];     // per-node logits (stride 41)

    for (int idx = threadIdx.x; idx < 16 * 40; idx += 256) {
        sW[idx]           = W2l[idx];
        sW[16 * 40 + idx] = W2r[idx];
    }
    if (threadIdx.x < 40) sB[threadIdx.x] = b2[threadIdx.x];

    int warpIn = threadIdx.x >> 5;
    int lane = threadIdx.x & 31;
    int half = lane >> 4;
    int l    = lane & 15;
    int grp  = l >> 2;
    int comp = l & 3;

    int blockBase = blockIdx.x * 16;
    int nodeLocal = (warpIn << 1) | half;
    int node  = blockBase + nodeLocal;
    bool valid = node < n;
    int nodeC = valid ? node : (n - 1);

    int deg0 = __ldg(&g_cnt[nodeC]);

    const uint2* __restrict__ Hh  = (const uint2*)g_h16;
    const int*   __restrict__ row = &g_csr[(size_t)nodeC * CAP];

    int idxA = __ldg(&row[l]);
    int idxB = __ldg(&row[l + 16]);

    float4 acc = make_float4(0.f, 0.f, 0.f, 0.f);
#pragma unroll
    for (int k = 0; k < 8; k++) {
        int s = grp + 4 * k;
        int src = (s < 16)
            ? __shfl_sync(0xffffffffu, idxA, (half << 4) | s)
            : __shfl_sync(0xffffffffu, idxB, (half << 4) | (s - 16));
        uint2 raw = __ldg(&Hh[(size_t)src * 4 + comp]);
        float2 f01 = __half22float2(*(__half2*)&raw.x);
        float2 f23 = __half22float2(*(__half2*)&raw.y);
        acc.x += f01.x; acc.y += f01.y; acc.z += f23.x; acc.w += f23.y;
    }
    if (deg0 > 32) {
        int dmax = deg0 < CAP ? deg0 : CAP;
        for (int s = 32 + grp; s < dmax; s += 4) {
            int src = __ldg(&row[s]);
            uint2 raw = __ldg(&Hh[(size_t)src * 4 + comp]);
            float2 f01 = __half22float2(*(__half2*)&raw.x);
            float2 f23 = __half22float2(*(__half2*)&raw.y);
            acc.x += f01.x; acc.y += f01.y; acc.z += f23.x; acc.w += f23.y;
        }
    }
#pragma unroll
    for (int off = 4; off < 16; off <<= 1) {
        acc.x += __shfl_xor_sync(0xffffffffu, acc.x, off);
        acc.y += __shfl_xor_sync(0xffffffffu, acc.y, off);
        acc.z += __shfl_xor_sync(0xffffffffu, acc.z, off);
        acc.w += __shfl_xor_sync(0xffffffffu, acc.w, off);
    }
    if (valid) {
        if (l < 4) {                      // a2 part (cols 0..15)
            float inv = 1.f / fmaxf((float)deg0, 1.f);
            *(float4*)&sF[nodeLocal * 36 + l * 4] =
                make_float4(acc.x * inv, acc.y * inv, acc.z * inv, acc.w * inv);
        } else if (l < 8) {               // h part (cols 16..31) from fp16 table
            int q = l - 4;
            uint2 raw = __ldg(&Hh[(size_t)(node + 1) * 4 + q]);
            float2 f01 = __half22float2(*(__half2*)&raw.x);
            float2 f23 = __half22float2(*(__half2*)&raw.y);
            *(float4*)&sF[nodeLocal * 36 + 16 + q * 4] =
                make_float4(f01.x, f01.y, f23.x, f23.y);
        }
    }
    __syncthreads();

    // Phase B: 160 quad items = 16 nodes x 10 class-quads
    if (threadIdx.x < 160) {
        int nd = threadIdx.x / 10;
        int q  = threadIdx.x - nd * 10;
        if (blockBase + nd < n) {
            const float* f = &sF[nd * 36];
            float4 a = *(const float4*)&sB[q * 4];
#pragma unroll 8
            for (int k = 0; k < 32; k++) {
                float fk = f[k];
                float4 w = *(const float4*)&sW[k * 40 + q * 4];
                a.x = fmaf(fk, w.x, a.x);
                a.y = fmaf(fk, w.y, a.y);
                a.z = fmaf(fk, w.z, a.z);
                a.w = fmaf(fk, w.w, a.w);
            }
            float* Lr = &sL[nd * 41 + q * 4];
            Lr[0] = a.x; Lr[1] = a.y; Lr[2] = a.z; Lr[3] = a.w;
        }
    }
    __syncthreads();

    // Phase C: log_softmax per node
    if (threadIdx.x < 16 && blockBase + (int)threadIdx.x < n) {
        float* Lr = &sL[threadIdx.x * 41];
        float m = Lr[0];
#pragma unroll
        for (int j = 1; j < 40; j++) m = fmaxf(m, Lr[j]);
        float s = 0.f;
#pragma unroll
        for (int j = 0; j < 40; j++) s += __expf(Lr[j] - m);
        float lse = m + __logf(s);
#pragma unroll
        for (int j = 0; j < 40; j++) Lr[j] -= lse;
    }
    __syncthreads();

    // Phase D: coalesced store
    int cnt = n - blockBase; if (cnt > 16) cnt = 16;
    int tot = cnt * 40;
    float* ob = out + (size_t)blockBase * 40;
    for (int i = threadIdx.x; i < tot; i += 256) {
        int nd = i / 40, j = i - nd * 40;
        ob[i] = sL[nd * 41 + j];
    }
}

// ---------------- launch ----------------------------------------------------
extern "C" void kernel_launch(void* const* d_in, const int* in_sizes, int n_in,
                              void* d_out, int out_size) {
    const float* x   = (const float*)d_in[0];
    const int*   ei  = (const int*)d_in[1];
    const float* W1l = (const float*)d_in[2];
    const float* b1  = (const float*)d_in[3];
    const float* W1r = (const float*)d_in[4];
    const float* W2l = (const float*)d_in[5];
    const float* b2  = (const float*)d_in[6];
    const float* W2r = (const float*)d_in[7];
    float* out = (float*)d_out;

    int n = in_sizes[0] / 128;
    int E = in_sizes[1] / 2;
    if (n > MAX_NODES) n = MAX_NODES;
    if (E > MAX_EDGES) E = MAX_EDGES;

    int pairs = (E + 1) / 2;
    int aggBlocks = (n + 15) / 16;

    cudaStream_t s2 = nullptr;
    cudaEvent_t eF = nullptr, eJ = nullptr;
    bool forked = (cudaStreamCreateWithFlags(&s2, cudaStreamNonBlocking) == cudaSuccess);
    if (forked) forked = (cudaEventCreateWithFlags(&eF, cudaEventDisableTiming) == cudaSuccess);
    if (forked) forked = (cudaEventCreateWithFlags(&eJ, cudaEventDisableTiming) == cudaSuccess);

    if (forked) {
        // build (main) || gemm1 (s2); both needed by agg1
        cudaEventRecord(eF, 0);
        cudaStreamWaitEvent(s2, eF, 0);
        gemm1_kernel<<<(n + 127) / 128, 256, 0, s2>>>(x, W1l, W1r, n);
        cudaEventRecord(eJ, s2);
        build_kernel<<<(pairs + 255) / 256, 256>>>(ei, E);
        cudaStreamWaitEvent(0, eJ, 0);

        agg1_kernel<<<aggBlocks, 256>>>(b1, n);
        agg2f_kernel<<<aggBlocks, 256>>>(W2l, b2, W2r, out, n);
        reset_kernel<<<832, 256>>>(n);
    } else {
        gemm1_kernel<<<(n + 127) / 128, 256>>>(x, W1l, W1r, n);
        build_kernel<<<(pairs + 255) / 256, 256>>>(ei, E);
        agg1_kernel<<<aggBlocks, 256>>>(b1, n);
        agg2f_kernel<<<aggBlocks, 256>>>(W2l, b2, W2r, out, n);
        reset_kernel<<<832, 256>>>(n);
    }

    if (eF) cudaEventDestroy(eF);
    if (eJ) cudaEventDestroy(eJ);
    if (s2) cudaStreamDestroy(s2);
}

// round 14
// speedup vs baseline: 1.2874x; 1.2874x over previous
#include <cuda_runtime.h>
#include <cuda_bf16.h>
#include <cuda_fp16.h>

#define MAX_NODES 100000
#define MAX_EDGES 1600000
#define CAP 64   // max neighbors stored per node; deg ~ Poisson(16), P(>64) ~ 1e-20

// ---------------- scratch (device globals; no allocation allowed) ----------
// Gather tables use rows 1..n for real nodes; ROW 0 IS THE DUMMY ZERO ROW.
// CSR pad value is 0 -> matches static zero-init; reset kernel restores the
// zero state at the end of every replay (overlapped with finish2).
__device__                int    g_cnt[MAX_NODES];                 // in-degree
__device__ __align__(16)  int    g_csr[MAX_NODES * CAP];           // src+1 lists
__device__ __align__(16)  __half g_Pl_h[(MAX_NODES + 1) * 16];     // pl fp16 (row0=dummy)
__device__ __align__(16)  float  g_Pr[MAX_NODES * 16];             // pr fp32
__device__ __align__(16)  float  g_h[MAX_NODES * 16];              // h fp32 (finish2)
__device__ __align__(16)  __half g_h16[(MAX_NODES + 1) * 16];      // h fp16 (row0=dummy)
__device__ __align__(16)  float  g_a2[MAX_NODES * 16];             // layer-2 mean-agg

// ---------------- K1: build bucketed CSR (one pass, 2 edges/thread) --------
__global__ void __launch_bounds__(256)
build_kernel(const int* __restrict__ ei, int E) {
    int i = blockIdx.x * blockDim.x + threadIdx.x;   // pair index
    int base = i * 2;
    if (base >= E) return;
    if (base + 1 < E) {
        int2 s2 = *(const int2*)&ei[base];
        int2 d2 = *(const int2*)&ei[E + base];
        int p0 = atomicAdd(&g_cnt[d2.x], 1);
        int p1 = atomicAdd(&g_cnt[d2.y], 1);
        if (p0 < CAP) g_csr[(size_t)d2.x * CAP + p0] = s2.x + 1;
        if (p1 < CAP) g_csr[(size_t)d2.y * CAP + p1] = s2.y + 1;
    } else {
        int src = ei[base];
        int dst = ei[E + base];
        int p = atomicAdd(&g_cnt[dst], 1);
        if (p < CAP) g_csr[(size_t)dst * CAP + p] = src + 1;
    }
}

// ---------------- K6: reset for next replay (overlapped w/ finish2) --------
__global__ void __launch_bounds__(256)
reset_kernel(int n) {
    int tid = blockIdx.x * blockDim.x + threadIdx.x;
    int stride = gridDim.x * blockDim.x;
    for (int i = tid; i < n; i += stride) g_cnt[i] = 0;
    int4 z4 = make_int4(0, 0, 0, 0);
    int tot = n * 8;                       // 8 int4 cover slots 0..31
    for (int i = tid; i < tot; i += stride) {
        int node = i >> 3, q = i & 7;
        ((int4*)&g_csr[(size_t)node * CAP])[q] = z4;
    }
}

// ---------------- bf16 split helper (for gemm1 inputs) ----------------------
__device__ __forceinline__ unsigned split_pack(float v0, float v1, unsigned& lo_out) {
    __nv_bfloat16 h0 = __float2bfloat16_rn(v0);
    __nv_bfloat16 h1 = __float2bfloat16_rn(v1);
    float r0 = v0 - __bfloat162float(h0);
    float r1 = v1 - __bfloat162float(h1);
    __nv_bfloat16 l0 = __float2bfloat16_rn(r0);
    __nv_bfloat16 l1 = __float2bfloat16_rn(r1);
    lo_out = (unsigned)__bfloat16_as_ushort(l0) | ((unsigned)__bfloat16_as_ushort(l1) << 16);
    return (unsigned)__bfloat16_as_ushort(h0) | ((unsigned)__bfloat16_as_ushort(h1) << 16);
}

__device__ __forceinline__ void mma_bf16(float c[4], unsigned a0, unsigned a1,
                                         unsigned a2, unsigned a3,
                                         unsigned b0, unsigned b1) {
    asm volatile(
        "mma.sync.aligned.m16n8k16.row.col.f32.bf16.bf16.f32 "
        "{%0,%1,%2,%3}, {%4,%5,%6,%7}, {%8,%9}, {%0,%1,%2,%3};"
        : "+f"(c[0]), "+f"(c[1]), "+f"(c[2]), "+f"(c[3])
        : "r"(a0), "r"(a1), "r"(a2), "r"(a3), "r"(b0), "r"(b1));
}

// ---------------- K2: P = x @ [W1l | W1r] via bf16-split tensor cores ------
__global__ void __launch_bounds__(256)
gemm1_kernel(const float* __restrict__ x,
             const float* __restrict__ W1l,
             const float* __restrict__ W1r, int n) {
    __shared__ unsigned sBhi[2048];
    __shared__ unsigned sBlo[2048];
    for (int idx = threadIdx.x; idx < 2048; idx += 256) {
        int lane  = idx & 31;
        int r     = (idx >> 5) & 1;
        int ntile = (idx >> 6) & 3;
        int kstep = idx >> 8;
        int t = lane & 3, gg = lane >> 2;
        int k = kstep * 16 + 2 * t + 8 * r;
        int j = ntile * 8 + gg;
        float w0 = (j < 16) ? W1l[k * 16 + j]       : W1r[k * 16 + (j - 16)];
        float w1 = (j < 16) ? W1l[(k + 1) * 16 + j] : W1r[(k + 1) * 16 + (j - 16)];
        unsigned lo;
        unsigned hi = split_pack(w0, w1, lo);
        sBhi[idx] = hi;
        sBlo[idx] = lo;
    }
    __syncthreads();

    int warp = threadIdx.x >> 5;
    int lane = threadIdx.x & 31;
    int row0 = (blockIdx.x * 8 + warp) * 16;
    if (row0 >= n) return;
    int g = lane >> 2;
    int t = lane & 3;

    int rA = row0 + g;      if (rA >= n) rA = n - 1;
    int rB = row0 + g + 8;  if (rB >= n) rB = n - 1;

    const float2* x2 = (const float2*)x;
    float c[4][4];
#pragma unroll
    for (int nt = 0; nt < 4; nt++)
#pragma unroll
        for (int q = 0; q < 4; q++) c[nt][q] = 0.f;

#pragma unroll
    for (int kstep = 0; kstep < 8; kstep++) {
        float2 p00 = x2[(size_t)rA * 64 + kstep * 8 + t];
        float2 p01 = x2[(size_t)rA * 64 + kstep * 8 + t + 4];
        float2 p10 = x2[(size_t)rB * 64 + kstep * 8 + t];
        float2 p11 = x2[(size_t)rB * 64 + kstep * 8 + t + 4];
        unsigned alo0, alo1, alo2, alo3;
        unsigned ahi0 = split_pack(p00.x, p00.y, alo0);
        unsigned ahi1 = split_pack(p10.x, p10.y, alo1);
        unsigned ahi2 = split_pack(p01.x, p01.y, alo2);
        unsigned ahi3 = split_pack(p11.x, p11.y, alo3);

#pragma unroll
        for (int nt = 0; nt < 4; nt++) {
            int base = ((kstep * 4 + nt) * 2) * 32 + lane;
            unsigned bhi0 = sBhi[base], bhi1 = sBhi[base + 32];
            unsigned blo0 = sBlo[base], blo1 = sBlo[base + 32];
            mma_bf16(c[nt], ahi0, ahi1, ahi2, ahi3, bhi0, bhi1);
            mma_bf16(c[nt], ahi0, ahi1, ahi2, ahi3, blo0, blo1);
            mma_bf16(c[nt], alo0, alo1, alo2, alo3, bhi0, bhi1);
        }
    }

    // pl -> fp16 table (shifted by +1 row); pr -> fp32 table
#pragma unroll
    for (int nt = 0; nt < 2; nt++) {        // cols 0..15 (pl)
        int j0 = nt * 8 + 2 * t;
        if (row0 + g < n) {
            __half2 hp = __float22half2_rn(make_float2(c[nt][0], c[nt][1]));
            *(__half2*)&g_Pl_h[(size_t)(row0 + g + 1) * 16 + j0] = hp;
        }
        if (row0 + g + 8 < n) {
            __half2 hp = __float22half2_rn(make_float2(c[nt][2], c[nt][3]));
            *(__half2*)&g_Pl_h[(size_t)(row0 + g + 9) * 16 + j0] = hp;
        }
    }
#pragma unroll
    for (int nt = 2; nt < 4; nt++) {        // cols 16..31 (pr)
        int j0 = (nt - 2) * 8 + 2 * t;
        if (row0 + g < n)
            *(float2*)&g_Pr[(size_t)(row0 + g) * 16 + j0] = make_float2(c[nt][0], c[nt][1]);
        if (row0 + g + 8 < n)
            *(float2*)&g_Pr[(size_t)(row0 + g + 8) * 16 + j0] = make_float2(c[nt][2], c[nt][3]);
    }
}

// ---------------- K3: agg1 + finish1 fused (R10 gather shape) ---------------
__global__ void __launch_bounds__(256)
agg1_kernel(const float* __restrict__ b1, int n) {
    int warpId = (blockIdx.x * blockDim.x + threadIdx.x) >> 5;
    int node0 = warpId * 2;
    if (node0 >= n) return;
    int lane = threadIdx.x & 31;
    int half = lane >> 4;
    int l    = lane & 15;
    int grp  = l >> 2;
    int comp = l & 3;

    int node  = node0 + half;
    bool valid = node < n;
    int nodeC = valid ? node : node0;

    int deg0 = __ldg(&g_cnt[nodeC]);

    const uint2* __restrict__ Ph  = (const uint2*)g_Pl_h;
    const int*   __restrict__ row = &g_csr[(size_t)nodeC * CAP];

    int idxA = __ldg(&row[l]);
    int idxB = __ldg(&row[l + 16]);

    float4 acc = make_float4(0.f, 0.f, 0.f, 0.f);
#pragma unroll
    for (int k = 0; k < 8; k++) {
        int s = grp + 4 * k;
        int src = (s < 16)
            ? __shfl_sync(0xffffffffu, idxA, (half << 4) | s)
            : __shfl_sync(0xffffffffu, idxB, (half << 4) | (s - 16));
        uint2 raw = __ldg(&Ph[(size_t)src * 4 + comp]);
        float2 f01 = __half22float2(*(__half2*)&raw.x);
        float2 f23 = __half22float2(*(__half2*)&raw.y);
        acc.x += f01.x; acc.y += f01.y; acc.z += f23.x; acc.w += f23.y;
    }
    if (deg0 > 32) {
        int dmax = deg0 < CAP ? deg0 : CAP;
        for (int s = 32 + grp; s < dmax; s += 4) {
            int src = __ldg(&row[s]);
            uint2 raw = __ldg(&Ph[(size_t)src * 4 + comp]);
            float2 f01 = __half22float2(*(__half2*)&raw.x);
            float2 f23 = __half22float2(*(__half2*)&raw.y);
            acc.x += f01.x; acc.y += f01.y; acc.z += f23.x; acc.w += f23.y;
        }
    }
#pragma unroll
    for (int off = 4; off < 16; off <<= 1) {
        acc.x += __shfl_xor_sync(0xffffffffu, acc.x, off);
        acc.y += __shfl_xor_sync(0xffffffffu, acc.y, off);
        acc.z += __shfl_xor_sync(0xffffffffu, acc.z, off);
        acc.w += __shfl_xor_sync(0xffffffffu, acc.w, off);
    }
    if (l < 4 && valid) {
        float inv = 1.f / fmaxf((float)deg0, 1.f);
        float4 pr = ((const float4*)g_Pr)[(size_t)node * 4 + l];
        float4 bb = ((const float4*)b1)[l];
        float4 hv;
        hv.x = fmaxf(fmaf(acc.x, inv, bb.x + pr.x), 0.f);
        hv.y = fmaxf(fmaf(acc.y, inv, bb.y + pr.y), 0.f);
        hv.z = fmaxf(fmaf(acc.z, inv, bb.z + pr.z), 0.f);
        hv.w = fmaxf(fmaf(acc.w, inv, bb.w + pr.w), 0.f);
        ((float4*)g_h)[(size_t)node * 4 + l] = hv;
        // fp16 copy for agg2's gather (row node+1; row 0 stays the zero dummy)
        uint2 packed;
        __half2 p01 = __float22half2_rn(make_float2(hv.x, hv.y));
        __half2 p23 = __float22half2_rn(make_float2(hv.z, hv.w));
        packed.x = *(unsigned*)&p01;
        packed.y = *(unsigned*)&p23;
        ((uint2*)g_h16)[(size_t)(node + 1) * 4 + l] = packed;
    }
}

// ---------------- K4: agg2 (R10 shape, fp16 gather of h) --------------------
__global__ void __launch_bounds__(256)
agg2_kernel(int n) {
    int warpId = (blockIdx.x * blockDim.x + threadIdx.x) >> 5;
    int node0 = warpId * 2;
    if (node0 >= n) return;
    int lane = threadIdx.x & 31;
    int half = lane >> 4;
    int l    = lane & 15;
    int grp  = l >> 2;
    int comp = l & 3;

    int node  = node0 + half;
    bool valid = node < n;
    int nodeC = valid ? node : node0;

    int deg0 = __ldg(&g_cnt[nodeC]);

    const uint2* __restrict__ Hh  = (const uint2*)g_h16;
    const int*   __restrict__ row = &g_csr[(size_t)nodeC * CAP];

    int idxA = __ldg(&row[l]);
    int idxB = __ldg(&row[l + 16]);

    float4 acc = make_float4(0.f, 0.f, 0.f, 0.f);
#pragma unroll
    for (int k = 0; k < 8; k++) {
        int s = grp + 4 * k;
        int src = (s < 16)
            ? __shfl_sync(0xffffffffu, idxA, (half << 4) | s)
            : __shfl_sync(0xffffffffu, idxB, (half << 4) | (s - 16));
        uint2 raw = __ldg(&Hh[(size_t)src * 4 + comp]);
        float2 f01 = __half22float2(*(__half2*)&raw.x);
        float2 f23 = __half22float2(*(__half2*)&raw.y);
        acc.x += f01.x; acc.y += f01.y; acc.z += f23.x; acc.w += f23.y;
    }
    if (deg0 > 32) {
        int dmax = deg0 < CAP ? deg0 : CAP;
        for (int s = 32 + grp; s < dmax; s += 4) {
            int src = __ldg(&row[s]);
            uint2 raw = __ldg(&Hh[(size_t)src * 4 + comp]);
            float2 f01 = __half22float2(*(__half2*)&raw.x);
            float2 f23 = __half22float2(*(__half2*)&raw.y);
            acc.x += f01.x; acc.y += f01.y; acc.z += f23.x; acc.w += f23.y;
        }
    }
#pragma unroll
    for (int off = 4; off < 16; off <<= 1) {
        acc.x += __shfl_xor_sync(0xffffffffu, acc.x, off);
        acc.y += __shfl_xor_sync(0xffffffffu, acc.y, off);
        acc.z += __shfl_xor_sync(0xffffffffu, acc.z, off);
        acc.w += __shfl_xor_sync(0xffffffffu, acc.w, off);
    }
    if (l < 4 && valid) {
        float inv = 1.f / fmaxf((float)deg0, 1.f);
        float4 o = make_float4(acc.x * inv, acc.y * inv, acc.z * inv, acc.w * inv);
        ((float4*)g_a2)[(size_t)node * 4 + l] = o;
    }
}

// ---------------- K5: out = log_softmax(a2@W2l + b2 + h@W2r) ----------------
// 256 nodes per 256-thread block: weight staging amortized 2x vs R12.
__global__ void __launch_bounds__(256)
finish2_kernel(const float* __restrict__ W2l,
               const float* __restrict__ b2,
               const float* __restrict__ W2r,
               float* __restrict__ out, int n) {
    __shared__ float sW[32 * 40];     // rows 0..15 = W2l, rows 16..31 = W2r
    __shared__ float sB[40];
    __shared__ float sOut[256 * 41];  // padded stride 41: conflict-free
    for (int idx = threadIdx.x; idx < 16 * 40; idx += 256) {
        sW[idx]           = W2l[idx];
        sW[16 * 40 + idx] = W2r[idx];
    }
    if (threadIdx.x < 40) sB[threadIdx.x] = b2[threadIdx.x];
    __syncthreads();

    int node = blockIdx.x * 256 + threadIdx.x;
    if (node < n) {
        float f[32];
        const float4* a4 = (const float4*)&g_a2[(size_t)node * 16];
        const float4* h4 = (const float4*)&g_h[(size_t)node * 16];
#pragma unroll
        for (int q = 0; q < 4; q++) {
            float4 v = a4[q];
            f[q * 4 + 0] = v.x; f[q * 4 + 1] = v.y;
            f[q * 4 + 2] = v.z; f[q * 4 + 3] = v.w;
        }
#pragma unroll
        for (int q = 0; q < 4; q++) {
            float4 v = h4[q];
            f[16 + q * 4 + 0] = v.x; f[16 + q * 4 + 1] = v.y;
            f[16 + q * 4 + 2] = v.z; f[16 + q * 4 + 3] = v.w;
        }

        float acc[40];
#pragma unroll
        for (int j = 0; j < 40; j++) acc[j] = sB[j];

#pragma unroll
        for (int k = 0; k < 32; k++) {
            float fk = f[k];
#pragma unroll
            for (int j = 0; j < 40; j += 4) {
                float4 w = *(const float4*)&sW[k * 40 + j];
                acc[j + 0] = fmaf(fk, w.x, acc[j + 0]);
                acc[j + 1] = fmaf(fk, w.y, acc[j + 1]);
                acc[j + 2] = fmaf(fk, w.z, acc[j + 2]);
                acc[j + 3] = fmaf(fk, w.w, acc[j + 3]);
            }
        }

        float m = acc[0];
#pragma unroll
        for (int j = 1; j < 40; j++) m = fmaxf(m, acc[j]);
        float s = 0.f;
#pragma unroll
        for (int j = 0; j < 40; j++) s += __expf(acc[j] - m);
        float lse = m + __logf(s);

        float* so = &sOut[threadIdx.x * 41];
#pragma unroll
        for (int j = 0; j < 40; j++) so[j] = acc[j] - lse;
    }
    __syncthreads();

    // coalesced copy smem -> global
    int base = blockIdx.x * 256;
    int cnt  = n - base; if (cnt > 256) cnt = 256;
    int tot  = cnt * 40;
    float* ob = out + (size_t)base * 40;
    for (int i = threadIdx.x; i < tot; i += 256) {
        int nd = i / 40, j = i - nd * 40;
        ob[i] = sOut[nd * 41 + j];
    }
}

// ---------------- launch ----------------------------------------------------
extern "C" void kernel_launch(void* const* d_in, const int* in_sizes, int n_in,
                              void* d_out, int out_size) {
    const float* x   = (const float*)d_in[0];
    const int*   ei  = (const int*)d_in[1];
    const float* W1l = (const float*)d_in[2];
    const float* b1  = (const float*)d_in[3];
    const float* W1r = (const float*)d_in[4];
    const float* W2l = (const float*)d_in[5];
    const float* b2  = (const float*)d_in[6];
    const float* W2r = (const float*)d_in[7];
    float* out = (float*)d_out;

    int n = in_sizes[0] / 128;
    int E = in_sizes[1] / 2;
    if (n > MAX_NODES) n = MAX_NODES;
    if (E > MAX_EDGES) E = MAX_EDGES;

    int pairs = (E + 1) / 2;
    int aggBlocks = (n + 15) / 16;  // 8 warps x 2 nodes per 256-thread block

    cudaStream_t s2 = nullptr;
    cudaEvent_t eF = nullptr, eJ = nullptr, eA = nullptr, eR = nullptr;
    bool forked = (cudaStreamCreateWithFlags(&s2, cudaStreamNonBlocking) == cudaSuccess);
    if (forked) forked = (cudaEventCreateWithFlags(&eF, cudaEventDisableTiming) == cudaSuccess);
    if (forked) forked = (cudaEventCreateWithFlags(&eJ, cudaEventDisableTiming) == cudaSuccess);
    if (forked) forked = (cudaEventCreateWithFlags(&eA, cudaEventDisableTiming) == cudaSuccess);
    if (forked) forked = (cudaEventCreateWithFlags(&eR, cudaEventDisableTiming) == cudaSuccess);

    if (forked) {
        // build (main) || gemm1 (s2); both needed by agg1
        cudaEventRecord(eF, 0);
        cudaStreamWaitEvent(s2, eF, 0);
        gemm1_kernel<<<(n + 127) / 128, 256, 0, s2>>>(x, W1l, W1r, n);
        cudaEventRecord(eJ, s2);
        build_kernel<<<(pairs + 255) / 256, 256>>>(ei, E);
        cudaStreamWaitEvent(0, eJ, 0);

        agg1_kernel<<<aggBlocks, 256>>>(b1, n);
        agg2_kernel<<<aggBlocks, 256>>>(n);

        // reset (s2, after last csr/cnt user) || finish2 (main)
        cudaEventRecord(eA, 0);
        cudaStreamWaitEvent(s2, eA, 0);
        reset_kernel<<<832, 256, 0, s2>>>(n);
        cudaEventRecord(eR, s2);
        finish2_kernel<<<(n + 255) / 256, 256>>>(W2l, b2, W2r, out, n);
        cudaStreamWaitEvent(0, eR, 0);
    } else {
        gemm1_kernel<<<(n + 127) / 128, 256>>>(x, W1l, W1r, n);
        build_kernel<<<(pairs + 255) / 256, 256>>>(ei, E);
        agg1_kernel<<<aggBlocks, 256>>>(b1, n);
        agg2_kernel<<<aggBlocks, 256>>>(n);
        finish2_kernel<<<(n + 255) / 256, 256>>>(W2l, b2, W2r, out, n);
        reset_kernel<<<832, 256>>>(n);
    }

    if (eF) cudaEventDestroy(eF);
    if (eJ) cudaEventDestroy(eJ);
    if (eA) cudaEventDestroy(eA);
    if (eR) cudaEventDestroy(eR);
    if (s2) cudaStreamDestroy(s2);
}

// round 15
// speedup vs baseline: 1.3345x; 1.0366x over previous
#include <cuda_runtime.h>
#include <cuda_bf16.h>
#include <cuda_fp16.h>

#define MAX_NODES 100000
#define MAX_EDGES 1600000
#define CAP 64   // max neighbors stored per node; deg ~ Poisson(16), P(>64) ~ 1e-20

// ---------------- scratch (device globals; no allocation allowed) ----------
// Gather tables use rows 1..n for real nodes; ROW 0 IS THE DUMMY ZERO ROW.
// CSR pad value is 0 -> matches static zero-init; reset kernel restores the
// zero state at the end of every replay (overlapped with finish2).
__device__                int    g_cnt[MAX_NODES];                 // in-degree
__device__ __align__(16)  int    g_csr[MAX_NODES * CAP];           // src+1 lists
__device__ __align__(16)  __half g_Pl_h[(MAX_NODES + 1) * 16];     // pl fp16 (row0=dummy)
__device__ __align__(16)  float  g_Pr[MAX_NODES * 16];             // pr fp32
__device__ __align__(16)  __half g_h16[(MAX_NODES + 1) * 16];      // h fp16 (row0=dummy)
__device__ __align__(16)  float  g_a2[MAX_NODES * 16];             // layer-2 mean-agg

// ---------------- K1: build bucketed CSR (one pass, 2 edges/thread) --------
__global__ void __launch_bounds__(256)
build_kernel(const int* __restrict__ ei, int E) {
    int i = blockIdx.x * blockDim.x + threadIdx.x;   // pair index
    int base = i * 2;
    if (base >= E) return;
    if (base + 1 < E) {
        int2 s2 = *(const int2*)&ei[base];
        int2 d2 = *(const int2*)&ei[E + base];
        int p0 = atomicAdd(&g_cnt[d2.x], 1);
        int p1 = atomicAdd(&g_cnt[d2.y], 1);
        if (p0 < CAP) g_csr[(size_t)d2.x * CAP + p0] = s2.x + 1;
        if (p1 < CAP) g_csr[(size_t)d2.y * CAP + p1] = s2.y + 1;
    } else {
        int src = ei[base];
        int dst = ei[E + base];
        int p = atomicAdd(&g_cnt[dst], 1);
        if (p < CAP) g_csr[(size_t)dst * CAP + p] = src + 1;
    }
}

// ---------------- K6: reset for next replay (overlapped w/ finish2) --------
__global__ void __launch_bounds__(256)
reset_kernel(int n) {
    int tid = blockIdx.x * blockDim.x + threadIdx.x;
    int stride = gridDim.x * blockDim.x;
    for (int i = tid; i < n; i += stride) g_cnt[i] = 0;
    int4 z4 = make_int4(0, 0, 0, 0);
    int tot = n * 8;                       // 8 int4 cover slots 0..31
    for (int i = tid; i < tot; i += stride) {
        int node = i >> 3, q = i & 7;
        ((int4*)&g_csr[(size_t)node * CAP])[q] = z4;
    }
}

// ---------------- bf16 split helper (for gemm1 inputs) ----------------------
__device__ __forceinline__ unsigned split_pack(float v0, float v1, unsigned& lo_out) {
    __nv_bfloat16 h0 = __float2bfloat16_rn(v0);
    __nv_bfloat16 h1 = __float2bfloat16_rn(v1);
    float r0 = v0 - __bfloat162float(h0);
    float r1 = v1 - __bfloat162float(h1);
    __nv_bfloat16 l0 = __float2bfloat16_rn(r0);
    __nv_bfloat16 l1 = __float2bfloat16_rn(r1);
    lo_out = (unsigned)__bfloat16_as_ushort(l0) | ((unsigned)__bfloat16_as_ushort(l1) << 16);
    return (unsigned)__bfloat16_as_ushort(h0) | ((unsigned)__bfloat16_as_ushort(h1) << 16);
}

__device__ __forceinline__ void mma_bf16(float c[4], unsigned a0, unsigned a1,
                                         unsigned a2, unsigned a3,
                                         unsigned b0, unsigned b1) {
    asm volatile(
        "mma.sync.aligned.m16n8k16.row.col.f32.bf16.bf16.f32 "
        "{%0,%1,%2,%3}, {%4,%5,%6,%7}, {%8,%9}, {%0,%1,%2,%3};"
        : "+f"(c[0]), "+f"(c[1]), "+f"(c[2]), "+f"(c[3])
        : "r"(a0), "r"(a1), "r"(a2), "r"(a3), "r"(b0), "r"(b1));
}

// ---------------- K2: P = x @ [W1l | W1r] via bf16-split tensor cores ------
__global__ void __launch_bounds__(256)
gemm1_kernel(const float* __restrict__ x,
             const float* __restrict__ W1l,
             const float* __restrict__ W1r, int n) {
    __shared__ unsigned sBhi[2048];
    __shared__ unsigned sBlo[2048];
    for (int idx = threadIdx.x; idx < 2048; idx += 256) {
        int lane  = idx & 31;
        int r     = (idx >> 5) & 1;
        int ntile = (idx >> 6) & 3;
        int kstep = idx >> 8;
        int t = lane & 3, gg = lane >> 2;
        int k = kstep * 16 + 2 * t + 8 * r;
        int j = ntile * 8 + gg;
        float w0 = (j < 16) ? W1l[k * 16 + j]       : W1r[k * 16 + (j - 16)];
        float w1 = (j < 16) ? W1l[(k + 1) * 16 + j] : W1r[(k + 1) * 16 + (j - 16)];
        unsigned lo;
        unsigned hi = split_pack(w0, w1, lo);
        sBhi[idx] = hi;
        sBlo[idx] = lo;
    }
    __syncthreads();

    int warp = threadIdx.x >> 5;
    int lane = threadIdx.x & 31;
    int row0 = (blockIdx.x * 8 + warp) * 16;
    if (row0 >= n) return;
    int g = lane >> 2;
    int t = lane & 3;

    int rA = row0 + g;      if (rA >= n) rA = n - 1;
    int rB = row0 + g + 8;  if (rB >= n) rB = n - 1;

    const float2* x2 = (const float2*)x;
    float c[4][4];
#pragma unroll
    for (int nt = 0; nt < 4; nt++)
#pragma unroll
        for (int q = 0; q < 4; q++) c[nt][q] = 0.f;

#pragma unroll
    for (int kstep = 0; kstep < 8; kstep++) {
        float2 p00 = x2[(size_t)rA * 64 + kstep * 8 + t];
        float2 p01 = x2[(size_t)rA * 64 + kstep * 8 + t + 4];
        float2 p10 = x2[(size_t)rB * 64 + kstep * 8 + t];
        float2 p11 = x2[(size_t)rB * 64 + kstep * 8 + t + 4];
        unsigned alo0, alo1, alo2, alo3;
        unsigned ahi0 = split_pack(p00.x, p00.y, alo0);
        unsigned ahi1 = split_pack(p10.x, p10.y, alo1);
        unsigned ahi2 = split_pack(p01.x, p01.y, alo2);
        unsigned ahi3 = split_pack(p11.x, p11.y, alo3);

#pragma unroll
        for (int nt = 0; nt < 4; nt++) {
            int base = ((kstep * 4 + nt) * 2) * 32 + lane;
            unsigned bhi0 = sBhi[base], bhi1 = sBhi[base + 32];
            unsigned blo0 = sBlo[base], blo1 = sBlo[base + 32];
            mma_bf16(c[nt], ahi0, ahi1, ahi2, ahi3, bhi0, bhi1);
            mma_bf16(c[nt], ahi0, ahi1, ahi2, ahi3, blo0, blo1);
            mma_bf16(c[nt], alo0, alo1, alo2, alo3, bhi0, bhi1);
        }
    }

    // pl -> fp16 table (shifted by +1 row); pr -> fp32 table
#pragma unroll
    for (int nt = 0; nt < 2; nt++) {        // cols 0..15 (pl)
        int j0 = nt * 8 + 2 * t;
        if (row0 + g < n) {
            __half2 hp = __float22half2_rn(make_float2(c[nt][0], c[nt][1]));
            *(__half2*)&g_Pl_h[(size_t)(row0 + g + 1) * 16 + j0] = hp;
        }
        if (row0 + g + 8 < n) {
            __half2 hp = __float22half2_rn(make_float2(c[nt][2], c[nt][3]));
            *(__half2*)&g_Pl_h[(size_t)(row0 + g + 9) * 16 + j0] = hp;
        }
    }
#pragma unroll
    for (int nt = 2; nt < 4; nt++) {        // cols 16..31 (pr)
        int j0 = (nt - 2) * 8 + 2 * t;
        if (row0 + g < n)
            *(float2*)&g_Pr[(size_t)(row0 + g) * 16 + j0] = make_float2(c[nt][0], c[nt][1]);
        if (row0 + g + 8 < n)
            *(float2*)&g_Pr[(size_t)(row0 + g + 8) * 16 + j0] = make_float2(c[nt][2], c[nt][3]);
    }
}

// ---------------- K3: agg1 + finish1 fused (R10 gather shape) ---------------
// h written ONLY to the fp16 table (consumed by agg2 and finish2).
__global__ void __launch_bounds__(256)
agg1_kernel(const float* __restrict__ b1, int n) {
    int warpId = (blockIdx.x * blockDim.x + threadIdx.x) >> 5;
    int node0 = warpId * 2;
    if (node0 >= n) return;
    int lane = threadIdx.x & 31;
    int half = lane >> 4;
    int l    = lane & 15;
    int grp  = l >> 2;
    int comp = l & 3;

    int node  = node0 + half;
    bool valid = node < n;
    int nodeC = valid ? node : node0;

    int deg0 = __ldg(&g_cnt[nodeC]);

    const uint2* __restrict__ Ph  = (const uint2*)g_Pl_h;
    const int*   __restrict__ row = &g_csr[(size_t)nodeC * CAP];

    int idxA = __ldg(&row[l]);
    int idxB = __ldg(&row[l + 16]);

    float4 acc = make_float4(0.f, 0.f, 0.f, 0.f);
#pragma unroll
    for (int k = 0; k < 8; k++) {
        int s = grp + 4 * k;
        int src = (s < 16)
            ? __shfl_sync(0xffffffffu, idxA, (half << 4) | s)
            : __shfl_sync(0xffffffffu, idxB, (half << 4) | (s - 16));
        uint2 raw = __ldg(&Ph[(size_t)src * 4 + comp]);
        float2 f01 = __half22float2(*(__half2*)&raw.x);
        float2 f23 = __half22float2(*(__half2*)&raw.y);
        acc.x += f01.x; acc.y += f01.y; acc.z += f23.x; acc.w += f23.y;
    }
    if (deg0 > 32) {
        int dmax = deg0 < CAP ? deg0 : CAP;
        for (int s = 32 + grp; s < dmax; s += 4) {
            int src = __ldg(&row[s]);
            uint2 raw = __ldg(&Ph[(size_t)src * 4 + comp]);
            float2 f01 = __half22float2(*(__half2*)&raw.x);
            float2 f23 = __half22float2(*(__half2*)&raw.y);
            acc.x += f01.x; acc.y += f01.y; acc.z += f23.x; acc.w += f23.y;
        }
    }
#pragma unroll
    for (int off = 4; off < 16; off <<= 1) {
        acc.x += __shfl_xor_sync(0xffffffffu, acc.x, off);
        acc.y += __shfl_xor_sync(0xffffffffu, acc.y, off);
        acc.z += __shfl_xor_sync(0xffffffffu, acc.z, off);
        acc.w += __shfl_xor_sync(0xffffffffu, acc.w, off);
    }
    if (l < 4 && valid) {
        float inv = 1.f / fmaxf((float)deg0, 1.f);
        float4 pr = ((const float4*)g_Pr)[(size_t)node * 4 + l];
        float4 bb = ((const float4*)b1)[l];
        float4 hv;
        hv.x = fmaxf(fmaf(acc.x, inv, bb.x + pr.x), 0.f);
        hv.y = fmaxf(fmaf(acc.y, inv, bb.y + pr.y), 0.f);
        hv.z = fmaxf(fmaf(acc.z, inv, bb.z + pr.z), 0.f);
        hv.w = fmaxf(fmaf(acc.w, inv, bb.w + pr.w), 0.f);
        uint2 packed;
        __half2 p01 = __float22half2_rn(make_float2(hv.x, hv.y));
        __half2 p23 = __float22half2_rn(make_float2(hv.z, hv.w));
        packed.x = *(unsigned*)&p01;
        packed.y = *(unsigned*)&p23;
        ((uint2*)g_h16)[(size_t)(node + 1) * 4 + l] = packed;
    }
}

// ---------------- K4: agg2 (R10 shape, fp16 gather of h) — PDL --------------
// Pre-work (deg + CSR index loads: build outputs, complete before agg1 even
// launched) runs while agg1 drains; cudaGridDependencySynchronize() gates the
// h16 gather on agg1 completion.
__global__ void __launch_bounds__(256)
agg2_kernel(int n) {
    int warpId = (blockIdx.x * blockDim.x + threadIdx.x) >> 5;
    int node0 = warpId * 2;
    if (node0 >= n) {
        cudaGridDependencySynchronize();
        return;
    }
    int lane = threadIdx.x & 31;
    int half = lane >> 4;
    int l    = lane & 15;
    int grp  = l >> 2;
    int comp = l & 3;

    int node  = node0 + half;
    bool valid = node < n;
    int nodeC = valid ? node : node0;

    int deg0 = __ldg(&g_cnt[nodeC]);

    const uint2* __restrict__ Hh  = (const uint2*)g_h16;
    const int*   __restrict__ row = &g_csr[(size_t)nodeC * CAP];

    int idxA = __ldg(&row[l]);
    int idxB = __ldg(&row[l + 16]);

    cudaGridDependencySynchronize();     // wait for agg1's h16 writes

    float4 acc = make_float4(0.f, 0.f, 0.f, 0.f);
#pragma unroll
    for (int k = 0; k < 8; k++) {
        int s = grp + 4 * k;
        int src = (s < 16)
            ? __shfl_sync(0xffffffffu, idxA, (half << 4) | s)
            : __shfl_sync(0xffffffffu, idxB, (half << 4) | (s - 16));
        uint2 raw = __ldg(&Hh[(size_t)src * 4 + comp]);
        float2 f01 = __half22float2(*(__half2*)&raw.x);
        float2 f23 = __half22float2(*(__half2*)&raw.y);
        acc.x += f01.x; acc.y += f01.y; acc.z += f23.x; acc.w += f23.y;
    }
    if (deg0 > 32) {
        int dmax = deg0 < CAP ? deg0 : CAP;
        for (int s = 32 + grp; s < dmax; s += 4) {
            int src = __ldg(&row[s]);
            uint2 raw = __ldg(&Hh[(size_t)src * 4 + comp]);
            float2 f01 = __half22float2(*(__half2*)&raw.x);
            float2 f23 = __half22float2(*(__half2*)&raw.y);
            acc.x += f01.x; acc.y += f01.y; acc.z += f23.x; acc.w += f23.y;
        }
    }
#pragma unroll
    for (int off = 4; off < 16; off <<= 1) {
        acc.x += __shfl_xor_sync(0xffffffffu, acc.x, off);
        acc.y += __shfl_xor_sync(0xffffffffu, acc.y, off);
        acc.z += __shfl_xor_sync(0xffffffffu, acc.z, off);
        acc.w += __shfl_xor_sync(0xffffffffu, acc.w, off);
    }
    if (l < 4 && valid) {
        float inv = 1.f / fmaxf((float)deg0, 1.f);
        float4 o = make_float4(acc.x * inv, acc.y * inv, acc.z * inv, acc.w * inv);
        ((float4*)g_a2)[(size_t)node * 4 + l] = o;
    }
}

// ---------------- K5: out = log_softmax(a2@W2l + b2 + h@W2r) — PDL ----------
// Weight staging (pure inputs) overlaps agg2's drain; grid-dep sync before
// reading g_a2 / g_h16.
__global__ void __launch_bounds__(256)
finish2_kernel(const float* __restrict__ W2l,
               const float* __restrict__ b2,
               const float* __restrict__ W2r,
               float* __restrict__ out, int n) {
    __shared__ float sW[32 * 40];     // rows 0..15 = W2l, rows 16..31 = W2r
    __shared__ float sB[40];
    __shared__ float sOut[256 * 41];  // padded stride 41: conflict-free
    for (int idx = threadIdx.x; idx < 16 * 40; idx += 256) {
        sW[idx]           = W2l[idx];
        sW[16 * 40 + idx] = W2r[idx];
    }
    if (threadIdx.x < 40) sB[threadIdx.x] = b2[threadIdx.x];

    cudaGridDependencySynchronize();     // wait for agg2 (and earlier) writes
    __syncthreads();

    int node = blockIdx.x * 256 + threadIdx.x;
    if (node < n) {
        float f[32];
        const float4* a4 = (const float4*)&g_a2[(size_t)node * 16];
        const uint2*  h4 = (const uint2*)&g_h16[(size_t)(node + 1) * 16];
#pragma unroll
        for (int q = 0; q < 4; q++) {
            float4 v = a4[q];
            f[q * 4 + 0] = v.x; f[q * 4 + 1] = v.y;
            f[q * 4 + 2] = v.z; f[q * 4 + 3] = v.w;
        }
#pragma unroll
        for (int q = 0; q < 4; q++) {
            uint2 raw = h4[q];
            float2 f01 = __half22float2(*(__half2*)&raw.x);
            float2 f23 = __half22float2(*(__half2*)&raw.y);
            f[16 + q * 4 + 0] = f01.x; f[16 + q * 4 + 1] = f01.y;
            f[16 + q * 4 + 2] = f23.x; f[16 + q * 4 + 3] = f23.y;
        }

        float acc[40];
#pragma unroll
        for (int j = 0; j < 40; j++) acc[j] = sB[j];

#pragma unroll
        for (int k = 0; k < 32; k++) {
            float fk = f[k];
#pragma unroll
            for (int j = 0; j < 40; j += 4) {
                float4 w = *(const float4*)&sW[k * 40 + j];
                acc[j + 0] = fmaf(fk, w.x, acc[j + 0]);
                acc[j + 1] = fmaf(fk, w.y, acc[j + 1]);
                acc[j + 2] = fmaf(fk, w.z, acc[j + 2]);
                acc[j + 3] = fmaf(fk, w.w, acc[j + 3]);
            }
        }

        float m = acc[0];
#pragma unroll
        for (int j = 1; j < 40; j++) m = fmaxf(m, acc[j]);
        float s = 0.f;
#pragma unroll
        for (int j = 0; j < 40; j++) s += __expf(acc[j] - m);
        float lse = m + __logf(s);

        float* so = &sOut[threadIdx.x * 41];
#pragma unroll
        for (int j = 0; j < 40; j++) so[j] = acc[j] - lse;
    }
    __syncthreads();

    // coalesced copy smem -> global
    int base = blockIdx.x * 256;
    int cnt  = n - base; if (cnt > 256) cnt = 256;
    int tot  = cnt * 40;
    float* ob = out + (size_t)base * 40;
    for (int i = threadIdx.x; i < tot; i += 256) {
        int nd = i / 40, j = i - nd * 40;
        ob[i] = sOut[nd * 41 + j];
    }
}

// ---------------- launch ----------------------------------------------------
template <typename... Args>
static void launch_pdl(void (*kern)(Args...), dim3 grid, dim3 block,
                       Args... args) {
    cudaLaunchConfig_t cfg = {};
    cfg.gridDim = grid;
    cfg.blockDim = block;
    cfg.stream = 0;
    cudaLaunchAttribute attr[1];
    attr[0].id = cudaLaunchAttributeProgrammaticStreamSerialization;
    attr[0].val.programmaticStreamSerializationAllowed = 1;
    cfg.attrs = attr;
    cfg.numAttrs = 1;
    if (cudaLaunchKernelEx(&cfg, kern, args...) != cudaSuccess) {
        kern<<<grid, block>>>(args...);   // fallback: plain launch (sync is no-op)
    }
}

extern "C" void kernel_launch(void* const* d_in, const int* in_sizes, int n_in,
                              void* d_out, int out_size) {
    const float* x   = (const float*)d_in[0];
    const int*   ei  = (const int*)d_in[1];
    const float* W1l = (const float*)d_in[2];
    const float* b1  = (const float*)d_in[3];
    const float* W1r = (const float*)d_in[4];
    const float* W2l = (const float*)d_in[5];
    const float* b2  = (const float*)d_in[6];
    const float* W2r = (const float*)d_in[7];
    float* out = (float*)d_out;

    int n = in_sizes[0] / 128;
    int E = in_sizes[1] / 2;
    if (n > MAX_NODES) n = MAX_NODES;
    if (E > MAX_EDGES) E = MAX_EDGES;

    int pairs = (E + 1) / 2;
    int aggBlocks = (n + 15) / 16;  // 8 warps x 2 nodes per 256-thread block

    cudaStream_t s2 = nullptr;
    cudaEvent_t eF = nullptr, eJ = nullptr, eA = nullptr, eR = nullptr;
    bool forked = (cudaStreamCreateWithFlags(&s2, cudaStreamNonBlocking) == cudaSuccess);
    if (forked) forked = (cudaEventCreateWithFlags(&eF, cudaEventDisableTiming) == cudaSuccess);
    if (forked) forked = (cudaEventCreateWithFlags(&eJ, cudaEventDisableTiming) == cudaSuccess);
    if (forked) forked = (cudaEventCreateWithFlags(&eA, cudaEventDisableTiming) == cudaSuccess);
    if (forked) forked = (cudaEventCreateWithFlags(&eR, cudaEventDisableTiming) == cudaSuccess);

    if (forked) {
        // build (main) || gemm1 (s2); both needed by agg1
        cudaEventRecord(eF, 0);
        cudaStreamWaitEvent(s2, eF, 0);
        gemm1_kernel<<<(n + 127) / 128, 256, 0, s2>>>(x, W1l, W1r, n);
        cudaEventRecord(eJ, s2);
        build_kernel<<<(pairs + 255) / 256, 256>>>(ei, E);
        cudaStreamWaitEvent(0, eJ, 0);

        agg1_kernel<<<aggBlocks, 256>>>(b1, n);
        launch_pdl(agg2_kernel, dim3(aggBlocks), dim3(256), n);

        // reset (s2, after last csr/cnt user) || finish2 (main, PDL on agg2)
        cudaEventRecord(eA, 0);
        cudaStreamWaitEvent(s2, eA, 0);
        reset_kernel<<<832, 256, 0, s2>>>(n);
        cudaEventRecord(eR, s2);
        launch_pdl(finish2_kernel, dim3((n + 255) / 256), dim3(256),
                   W2l, b2, W2r, out, n);
        cudaStreamWaitEvent(0, eR, 0);
    } else {
        gemm1_kernel<<<(n + 127) / 128, 256>>>(x, W1l, W1r, n);
        build_kernel<<<(pairs + 255) / 256, 256>>>(ei, E);
        agg1_kernel<<<aggBlocks, 256>>>(b1, n);
        agg2_kernel<<<aggBlocks, 256>>>(n);
        finish2_kernel<<<(n + 255) / 256, 256>>>(W2l, b2, W2r, out, n);
        reset_kernel<<<832, 256>>>(n);
    }

    if (eF) cudaEventDestroy(eF);
    if (eJ) cudaEventDestroy(eJ);
    if (eA) cudaEventDestroy(eA);
    if (eR) cudaEventDestroy(eR);
    if (s2) cudaStreamDestroy(s2);
}